// round 7
// baseline (speedup 1.0000x reference)
#include <cuda_runtime.h>

#define NROWS 16384
#define HDIM  128
#define NH    (NROWS * HDIM)        // 2097152
#define OCC   4                     // blocks per SM (enforced via __launch_bounds__)
#define NBLK  (148 * OCC)           // 592 — all co-resident -> spin barrier safe
#define WPB   8
#define NWARPS (NBLK * WPB)         // 4736
#define ITERS 4                     // ceil(16384 / 4736)

// Scratch (no allocations allowed) — __device__ globals.
__device__ float g_ys_part[NBLK * HDIM];    // per-block partial of sum_j y_j
__device__ float g_sy_part[NBLK];           // per-block partial of sum_j ||y_j||^2
__device__ float g_dg_part[NBLK];           // per-block partial of sum_i diag_i
__device__ float g_ys[HDIM];                // sum_j y_j
__device__ float g_SY;                      // sum_j ||y_j||^2
__device__ float g_nce_part[NBLK];
// Grid-barrier state. Counters reset by the releasing block each launch so the
// kernel is graph-replay safe; g_gen monotonically increases (wrap is fine).
__device__ unsigned g_c1 = 0, g_c2 = 0, g_gen = 0;

__device__ __forceinline__ float wred(float v) {
#pragma unroll
    for (int o = 16; o; o >>= 1) v += __shfl_xor_sync(0xffffffffu, v, o);
    return v;
}

__global__ void __launch_bounds__(256, OCC)
fused(const float4* __restrict__ enc, const float4* __restrict__ dec,
      float* __restrict__ out) {
    const int warp = threadIdx.x >> 5, lane = threadIdx.x & 31;
    const int gwarp = blockIdx.x * WPB + warp;
    float4* out4 = (float4*)out;

    __shared__ float4 s_ys[WPB][32];
    __shared__ float   s_sy[WPB], s_dg[WPB], s_acc[WPB];
    __shared__ float   s_red[256];
    __shared__ unsigned s_flag;

    unsigned start_gen = 0;
    if (threadIdx.x == 0) start_gen = *(volatile unsigned*)&g_gen;

    // ---------------- Phase 1: bi-sum, outputs, per-row stats, block partials
    float xn_r[ITERS], dg_r[ITERS];      // per-row ||x||^2 and diag, kept in regs
    float4 ys_acc = make_float4(0.f, 0.f, 0.f, 0.f);
    float sy_acc = 0.f, dg_acc = 0.f;

#pragma unroll
    for (int it = 0; it < ITERS; it++) {
        const int row = gwarp + it * NWARPS;
        xn_r[it] = 0.f; dg_r[it] = 0.f;
        if (row < NROWS) {
            const float4 e0 = enc[row * 64 + lane];
            const float4 e1 = enc[row * 64 + 32 + lane];
            const float4 d0 = dec[row * 64 + lane];
            const float4 d1 = dec[row * 64 + 32 + lane];
            float4 x = make_float4(e0.x + e1.x, e0.y + e1.y, e0.z + e1.z, e0.w + e1.w);
            float4 y = make_float4(d0.x + d1.x, d0.y + d1.y, d0.z + d1.z, d0.w + d1.w);

            out4[row * 32 + lane]                 = x;  // bi_enc (output 0)
            out4[(NH >> 2) + row * 32 + lane]     = x;  // bi_enc (output 1)
            out4[2 * (NH >> 2) + row * 32 + lane] = y;  // bi_dec (output 2)

            float xn = x.x * x.x + x.y * x.y + x.z * x.z + x.w * x.w;
            float yn = y.x * y.y * 0.f + y.x * y.x + y.y * y.y + y.z * y.z + y.w * y.w;
            float dd = x.x * y.x + x.y * y.y + x.z * y.z + x.w * y.w;
            xn = wred(xn); yn = wred(yn); dd = wred(dd);

            ys_acc.x += y.x; ys_acc.y += y.y; ys_acc.z += y.z; ys_acc.w += y.w;

            xn_r[it] = xn;                      // full sum on all lanes (xor shuffle)
            dg_r[it] = xn + yn - 2.f * dd;
            if (lane == 0) { sy_acc += yn; dg_acc += dg_r[it]; }
        }
    }

    s_ys[warp][lane] = ys_acc;
    if (lane == 0) { s_sy[warp] = sy_acc; s_dg[warp] = dg_acc; }
    __syncthreads();

    if (threadIdx.x < 32) {
        float4 a = s_ys[0][threadIdx.x];
#pragma unroll
        for (int w = 1; w < WPB; w++) {
            float4 v = s_ys[w][threadIdx.x];
            a.x += v.x; a.y += v.y; a.z += v.z; a.w += v.w;
        }
        ((float4*)g_ys_part)[blockIdx.x * 32 + threadIdx.x] = a;
        __threadfence();
    } else if (threadIdx.x == 32) {
        float s = 0.f;
#pragma unroll
        for (int w = 0; w < WPB; w++) s += s_sy[w];
        g_sy_part[blockIdx.x] = s;
        __threadfence();
    } else if (threadIdx.x == 33) {
        float s = 0.f;
#pragma unroll
        for (int w = 0; w < WPB; w++) s += s_dg[w];
        g_dg_part[blockIdx.x] = s;
        __threadfence();
    }
    __syncthreads();

    // ---------------- Arrival: last block reduces the mid partials
    if (threadIdx.x == 0) s_flag = (atomicAdd(&g_c1, 1) == NBLK - 1);
    __syncthreads();

    if (s_flag) {
        // ys column reduce: 2 threads per column, NBLK/2 partial rows each (L2-hot).
        const int col = threadIdx.x & 127, half = threadIdx.x >> 7;
        float s = 0.f;
#pragma unroll 4
        for (int b = half * (NBLK / 2); b < (half + 1) * (NBLK / 2); b++)
            s += g_ys_part[b * HDIM + col];
        s_red[threadIdx.x] = s;
        __syncthreads();
        if (threadIdx.x < 128) {
            g_ys[threadIdx.x] = s_red[threadIdx.x] + s_red[threadIdx.x + 128];
            __threadfence();
        }
        __syncthreads();

        // SY reduce (NBLK = 592 partials)
        {
            float s2 = 0.f;
            for (int b = threadIdx.x; b < NBLK; b += 256) s2 += g_sy_part[b];
            s_red[threadIdx.x] = s2;
        }
        __syncthreads();
        for (int st = 128; st; st >>= 1) {
            if (threadIdx.x < st) s_red[threadIdx.x] += s_red[threadIdx.x + st];
            __syncthreads();
        }
        if (threadIdx.x == 0) g_SY = s_red[0];
        __syncthreads();

        // diag-sum reduce -> diagonal_loss
        {
            float s2 = 0.f;
            for (int b = threadIdx.x; b < NBLK; b += 256) s2 += g_dg_part[b];
            s_red[threadIdx.x] = s2;
        }
        __syncthreads();
        for (int st = 128; st; st >>= 1) {
            if (threadIdx.x < st) s_red[threadIdx.x] += s_red[threadIdx.x + st];
            __syncthreads();
        }
        if (threadIdx.x == 0) {
            out[3 * NH + 1] = -s_red[0] / (float)NROWS;
            g_c1 = 0;                       // reset for next graph replay
            __threadfence();
            atomicAdd(&g_gen, 1);           // release
        }
    }

    // ---------------- Spin barrier (all blocks resident -> cannot deadlock)
    if (threadIdx.x == 0) {
        while (*(volatile unsigned*)&g_gen == start_gen) { }
        __threadfence();
    }
    __syncthreads();

    // ---------------- Phase 2: closed-form row loss; x re-read from L2-hot out
    const float4 ysl = ((const float4*)g_ys)[lane];
    const float SY = g_SY;

    float acc = 0.f;
#pragma unroll
    for (int it = 0; it < ITERS; it++) {
        const int row = gwarp + it * NWARPS;
        if (row < NROWS) {
            const float4 x = out4[row * 32 + lane];   // bi_enc, just written -> L2 hit
            float dd = x.x * ysl.x + x.y * ysl.y + x.z * ysl.z + x.w * ysl.w;
            dd = wred(dd);
            if (lane == 0) {
                float rowsum = (float)NROWS * xn_r[it] + SY - 2.f * dd;
                float rl = 5.f - rowsum + 10.f * dg_r[it];
                acc += fmaxf(rl, 0.f);
            }
        }
    }

    if (lane == 0) s_acc[warp] = acc;
    __syncthreads();
    if (threadIdx.x == 0) {
        float s = 0.f;
#pragma unroll
        for (int w = 0; w < WPB; w++) s += s_acc[w];
        g_nce_part[blockIdx.x] = s;
        __threadfence();
        s_flag = (atomicAdd(&g_c2, 1) == NBLK - 1);
    }
    __syncthreads();

    if (s_flag) {
        float s2 = 0.f;
        for (int b = threadIdx.x; b < NBLK; b += 256) s2 += g_nce_part[b];
        s_red[threadIdx.x] = s2;
        __syncthreads();
        for (int st = 128; st; st >>= 1) {
            if (threadIdx.x < st) s_red[threadIdx.x] += s_red[threadIdx.x + st];
            __syncthreads();
        }
        if (threadIdx.x == 0) {
            out[3 * NH] = s_red[0];
            g_c2 = 0;                       // reset for next graph replay
        }
    }
}

extern "C" void kernel_launch(void* const* d_in, const int* in_sizes, int n_in,
                              void* d_out, int out_size) {
    const float4* enc = (const float4*)d_in[0];
    const float4* dec = (const float4*)d_in[1];
    float* out = (float*)d_out;

    fused<<<NBLK, 256>>>(enc, dec, out);
}

// round 9
// speedup vs baseline: 1.2982x; 1.2982x over previous
#include <cuda_runtime.h>

#define NROWS 16384
#define HDIM  128
#define NH    (NROWS * HDIM)        // 2097152
#define OCC   4                     // CTAs per SM (enforced by __launch_bounds__)
#define NBLK  (148 * OCC)           // 592 — all co-resident -> spin barrier safe
#define WPB   8
#define NWARPS (NBLK * WPB)         // 4736
#define ITERS 4                     // ceil(16384 / 4736)

// Atomic accumulators (no serial reducer). Reset by the last phase-2 block so
// the kernel is graph-replay safe (next replay is stream-ordered after this one).
__device__ float g_ys[HDIM];        // sum_j y_j
__device__ float g_SY  = 0.f;       // sum_j ||y_j||^2
__device__ float g_dg  = 0.f;       // sum_i diag_i
__device__ float g_nce = 0.f;       // sum_i max(0, rowloss_i)
__device__ unsigned g_c1 = 0, g_c2 = 0;

__device__ __forceinline__ float wred(float v) {
#pragma unroll
    for (int o = 16; o; o >>= 1) v += __shfl_xor_sync(0xffffffffu, v, o);
    return v;
}

__global__ void __launch_bounds__(256, OCC)
fused(const float4* __restrict__ enc, const float4* __restrict__ dec,
      float* __restrict__ out) {
    const int warp = threadIdx.x >> 5, lane = threadIdx.x & 31;
    const int gwarp = blockIdx.x * WPB + warp;
    float4* out4 = (float4*)out;

    __shared__ float4 s_x[WPB][ITERS][32];   // 16 KB: x tiles for phase 2
    __shared__ float4 s_ys[WPB][32];
    __shared__ float   s_sy[WPB], s_dg[WPB], s_acc[WPB];
    __shared__ unsigned s_flag;

    // ---------------- Phase 1: bi-sum, outputs, per-row stats
    float xn_r[ITERS], dg_r[ITERS];          // per-row ||x||^2, diag (in regs)
    float4 ys_acc = make_float4(0.f, 0.f, 0.f, 0.f);
    float sy_acc = 0.f, dg_acc = 0.f;

#pragma unroll
    for (int it = 0; it < ITERS; it++) {
        const int row = gwarp + it * NWARPS;
        xn_r[it] = 0.f; dg_r[it] = 0.f;
        if (row < NROWS) {
            const float4 e0 = enc[row * 64 + lane];
            const float4 e1 = enc[row * 64 + 32 + lane];
            const float4 d0 = dec[row * 64 + lane];
            const float4 d1 = dec[row * 64 + 32 + lane];
            float4 x = make_float4(e0.x + e1.x, e0.y + e1.y, e0.z + e1.z, e0.w + e1.w);
            float4 y = make_float4(d0.x + d1.x, d0.y + d1.y, d0.z + d1.z, d0.w + d1.w);

            out4[row * 32 + lane]                 = x;  // bi_enc (output 0)
            out4[(NH >> 2) + row * 32 + lane]     = x;  // bi_enc (output 1)
            out4[2 * (NH >> 2) + row * 32 + lane] = y;  // bi_dec (output 2)
            s_x[warp][it][lane] = x;                    // keep for phase 2

            float xn = x.x * x.x + x.y * x.y + x.z * x.z + x.w * x.w;
            float yn = y.x * y.x + y.y * y.y + y.z * y.z + y.w * y.w;
            float dd = x.x * y.x + x.y * y.y + x.z * y.z + x.w * y.w;
            xn = wred(xn); yn = wred(yn); dd = wred(dd);

            ys_acc.x += y.x; ys_acc.y += y.y; ys_acc.z += y.z; ys_acc.w += y.w;
            xn_r[it] = xn;                      // full sums on all lanes (xor shuffle)
            dg_r[it] = xn + yn - 2.f * dd;
            if (lane == 0) { sy_acc += yn; dg_acc += dg_r[it]; }
        }
    }

    s_ys[warp][lane] = ys_acc;
    if (lane == 0) { s_sy[warp] = sy_acc; s_dg[warp] = dg_acc; }
    __syncthreads();

    // Block-level combine, then one RED per scalar / 128 REDs for ys.
    if (threadIdx.x < 32) {
        float4 a = s_ys[0][threadIdx.x];
#pragma unroll
        for (int w = 1; w < WPB; w++) {
            float4 v = s_ys[w][threadIdx.x];
            a.x += v.x; a.y += v.y; a.z += v.z; a.w += v.w;
        }
        atomicAdd(&g_ys[4 * threadIdx.x + 0], a.x);
        atomicAdd(&g_ys[4 * threadIdx.x + 1], a.y);
        atomicAdd(&g_ys[4 * threadIdx.x + 2], a.z);
        atomicAdd(&g_ys[4 * threadIdx.x + 3], a.w);
    } else if (threadIdx.x == 32) {
        float s = 0.f;
#pragma unroll
        for (int w = 0; w < WPB; w++) s += s_sy[w];
        atomicAdd(&g_SY, s);
    } else if (threadIdx.x == 33) {
        float s = 0.f;
#pragma unroll
        for (int w = 0; w < WPB; w++) s += s_dg[w];
        atomicAdd(&g_dg, s);
    }
    __threadfence();
    __syncthreads();

    // ---------------- Grid barrier 1 (ticket counter; no work in critical path)
    if (threadIdx.x == 0) {
        unsigned old = atomicAdd(&g_c1, 1);
        if (old == NBLK - 1) {
            // Everyone has fenced + added before incrementing: g_dg is final.
            out[3 * NH + 1] = -atomicAdd(&g_dg, 0.f) / (float)NROWS;
        }
        while (*(volatile unsigned*)&g_c1 < NBLK) { }
        __threadfence();
    }
    __syncthreads();

    // ---------------- Phase 2: closed-form row loss from smem-held x
    const float4 ysl = __ldcg(((const float4*)g_ys) + lane);
    const float SY = __ldcg(&g_SY);

    float acc = 0.f;
#pragma unroll
    for (int it = 0; it < ITERS; it++) {
        const int row = gwarp + it * NWARPS;
        if (row < NROWS) {
            const float4 x = s_x[warp][it][lane];
            float dd = x.x * ysl.x + x.y * ysl.y + x.z * ysl.z + x.w * ysl.w;
            dd = wred(dd);
            if (lane == 0) {
                float rowsum = (float)NROWS * xn_r[it] + SY - 2.f * dd;
                float rl = 5.f - rowsum + 10.f * dg_r[it];
                acc += fmaxf(rl, 0.f);
            }
        }
    }

    if (lane == 0) s_acc[warp] = acc;
    __syncthreads();
    if (threadIdx.x == 0) {
        float s = 0.f;
#pragma unroll
        for (int w = 0; w < WPB; w++) s += s_acc[w];
        atomicAdd(&g_nce, s);
        __threadfence();
        unsigned old = atomicAdd(&g_c2, 1);
        s_flag = (old == NBLK - 1);
    }
    __syncthreads();

    // Last block: publish nce and reset all state for the next graph replay.
    if (s_flag) {
        if (threadIdx.x < HDIM) {
            g_ys[threadIdx.x] = 0.f;
        } else if (threadIdx.x == HDIM) {
            out[3 * NH] = atomicAdd(&g_nce, 0.f);   // all adds precede c2 increments
            g_nce = 0.f;
        } else if (threadIdx.x == HDIM + 1) {
            g_SY = 0.f;
        } else if (threadIdx.x == HDIM + 2) {
            g_dg = 0.f;
        } else if (threadIdx.x == HDIM + 3) {
            g_c1 = 0;
            g_c2 = 0;
        }
    }
}

extern "C" void kernel_launch(void* const* d_in, const int* in_sizes, int n_in,
                              void* d_out, int out_size) {
    const float4* enc = (const float4*)d_in[0];
    const float4* dec = (const float4*)d_in[1];
    float* out = (float*)d_out;

    fused<<<NBLK, 256>>>(enc, dec, out);
}